// round 14
// baseline (speedup 1.0000x reference)
#include <cuda_runtime.h>
#include <math.h>

#define HOPLEN 256
#define NBINS  1025
#define MAXT   8193
#define NLAG   511
#define NC     1024

__device__ float g_f0[MAXT];

// ---------------------------------------------------------------------------
// Compile-time twiddle table: twm[j] = exp(-i*pi*j/1024), j in [0,2048).
// ---------------------------------------------------------------------------
struct alignas(16) TwTab { float2 v[2048]; };

constexpr double tp_sin(double x) {
    double t = x, s = x;
    for (int k = 1; k <= 10; ++k) { t = -t * x * x / ((2.0 * k) * (2.0 * k + 1.0)); s += t; }
    return s;
}
constexpr double tp_cos(double x) {
    double t = 1.0, s = 1.0;
    for (int k = 1; k <= 10; ++k) { t = -t * x * x / ((2.0 * k - 1.0) * (2.0 * k)); s += t; }
    return s;
}
constexpr TwTab make_twtab() {
    TwTab tab{};
    const double PI = 3.14159265358979323846264338327950288;
    for (int j = 0; j < 2048; ++j) {
        int q = (j >> 9) & 3;
        int r = j & 511;
        double c = 0.0, s = 0.0;
        if (r <= 256) { double x = PI * r / 1024.0;         c = tp_cos(x); s = tp_sin(x); }
        else          { double x = PI * (512 - r) / 1024.0; c = tp_sin(x); s = tp_cos(x); }
        double ct = 0.0, st = 0.0;
        switch (q) {
            case 0:  ct = c;  st = s;  break;
            case 1:  ct = -s; st = c;  break;
            case 2:  ct = -c; st = -s; break;
            default: ct = s;  st = -c; break;
        }
        tab.v[j].x = (float)ct;
        tab.v[j].y = (float)(-st);
    }
    return tab;
}
__device__ constexpr TwTab g_twc = make_twtab();

__device__ __forceinline__ float2 cmul(float2 a, float2 b) {
    return make_float2(a.x * b.x - a.y * b.y, a.x * b.y + a.y * b.x);
}
__device__ __forceinline__ int swz(int i) { return i ^ ((i >> 4) & 15); }

// reflect-handling load (boundary blocks only)
__device__ __forceinline__ float2 load_pt_refl(const float* __restrict__ audio, int n,
                                               int start, const float2* __restrict__ twm,
                                               int x) {
    int j0 = 2 * x;
    int i0 = start + j0, i1 = i0 + 1;
    if (i0 < 0) i0 = -i0; else if (i0 >= n) i0 = 2 * n - 2 - i0;
    if (i1 < 0) i1 = -i1; else if (i1 >= n) i1 = 2 * n - 2 - i1;
    float4 tv = *(const float4*)(twm + j0);
    return make_float2(audio[i0] * (0.5f - 0.5f * tv.x),
                       audio[i1] * (0.5f - 0.5f * tv.z));
}
// fast interior load: start even -> float2-aligned vector load, no clamps
__device__ __forceinline__ float2 load_pt_fast(const float2* __restrict__ audio2,
                                               const float2* __restrict__ twm, int x) {
    float2 av = __ldg(audio2 + x);
    float4 tv = *(const float4*)(twm + 2 * x);
    return make_float2(av.x * (0.5f - 0.5f * tv.x),
                       av.y * (0.5f - 0.5f * tv.z));
}

__device__ __forceinline__ void bfly4(float2 a0, float2 a1, float2 a2, float2 a3,
                                      float2& y0, float2& y1, float2& y2, float2& y3) {
    float2 s02 = make_float2(a0.x + a2.x, a0.y + a2.y);
    float2 d02 = make_float2(a0.x - a2.x, a0.y - a2.y);
    float2 s13 = make_float2(a1.x + a3.x, a1.y + a3.y);
    float2 d13 = make_float2(a1.x - a3.x, a1.y - a3.y);
    y0 = make_float2(s02.x + s13.x, s02.y + s13.y);
    y2 = make_float2(s02.x - s13.x, s02.y - s13.y);
    y1 = make_float2(d02.x + d13.y, d02.y - d13.x);
    y3 = make_float2(d02.x - d13.y, d02.y + d13.x);
}

template<int S, bool SWIN, bool SWOUT>
__device__ __forceinline__ void fft_pass16(const float2* __restrict__ src,
                                           float2* __restrict__ dst,
                                           const float2* __restrict__ twm, int c) {
    const int q = c & (S - 1);
    float2 t[4][4];
    #pragma unroll
    for (int j = 0; j < 4; ++j) {
        const int b = c + 64 * j;
        float2 a0 = src[SWIN ? swz(b)       : (b)];
        float2 a1 = src[SWIN ? swz(b + 256) : (b + 256)];
        float2 a2 = src[SWIN ? swz(b + 512) : (b + 512)];
        float2 a3 = src[SWIN ? swz(b + 768) : (b + 768)];
        float2 y0, y1, y2, y3;
        bfly4(a0, a1, a2, a3, y0, y1, y2, y3);
        const int p = b - q;
        t[j][0] = y0;
        t[j][1] = cmul(twm[2 * p], y1);
        t[j][2] = cmul(twm[4 * p], y2);
        t[j][3] = cmul(twm[6 * p], y3);
    }
    #pragma unroll
    for (int rh = 0; rh < 4; ++rh) {
        const int b4 = 4 * c - 3 * q + S * rh;
        const int q4 = b4 & (4 * S - 1);
        const int p4 = b4 - q4;
        float2 y0, y1, y2, y3;
        bfly4(t[0][rh], t[1][rh], t[2][rh], t[3][rh], y0, y1, y2, y3);
        const int base = 4 * p4 + q4;
        dst[SWOUT ? swz(base)          : (base)]          = y0;
        dst[SWOUT ? swz(base + 4 * S)  : (base + 4 * S)]  = cmul(twm[2 * p4], y1);
        dst[SWOUT ? swz(base + 8 * S)  : (base + 8 * S)]  = cmul(twm[4 * p4], y2);
        dst[SWOUT ? swz(base + 12 * S) : (base + 12 * S)] = cmul(twm[6 * p4], y3);
    }
}

template<bool REFL>
__device__ __forceinline__ void fft_pass16_load(const float* __restrict__ audio, int n,
                                                int start, float2* __restrict__ dst,
                                                const float2* __restrict__ twm, int c) {
    const float2* audio2 = (const float2*)(audio + start);   // start even
    float2 t[4][4];
    #pragma unroll
    for (int j = 0; j < 4; ++j) {
        const int b = c + 64 * j;
        float2 a0, a1, a2, a3;
        if (REFL) {
            a0 = load_pt_refl(audio, n, start, twm, b);
            a1 = load_pt_refl(audio, n, start, twm, b + 256);
            a2 = load_pt_refl(audio, n, start, twm, b + 512);
            a3 = load_pt_refl(audio, n, start, twm, b + 768);
        } else {
            a0 = load_pt_fast(audio2, twm, b);
            a1 = load_pt_fast(audio2, twm, b + 256);
            a2 = load_pt_fast(audio2, twm, b + 512);
            a3 = load_pt_fast(audio2, twm, b + 768);
        }
        float2 y0, y1, y2, y3;
        bfly4(a0, a1, a2, a3, y0, y1, y2, y3);
        t[j][0] = y0;
        t[j][1] = cmul(twm[2 * b], y1);
        t[j][2] = cmul(twm[4 * b], y2);
        t[j][3] = cmul(twm[6 * b], y3);
    }
    #pragma unroll
    for (int rh = 0; rh < 4; ++rh) {
        float2 y0, y1, y2, y3;
        bfly4(t[0][rh], t[1][rh], t[2][rh], t[3][rh], y0, y1, y2, y3);
        const int p4 = 4 * c;
        const int base = 4 * p4 + rh;
        dst[swz(base)]      = y0;
        dst[swz(base + 4)]  = cmul(twm[2 * p4], y1);
        dst[swz(base + 8)]  = cmul(twm[4 * p4], y2);
        dst[swz(base + 12)] = cmul(twm[6 * p4], y3);
    }
}

__device__ __forceinline__ void pairmag(float2 Zk, float2 Zm, float2 W,
                                        float& mk, float& mp) {
    float Er = 0.5f * (Zk.x + Zm.x);
    float Ei = 0.5f * (Zk.y - Zm.y);
    float u  = Zk.x - Zm.x;
    float v  = Zk.y + Zm.y;
    float P  = 0.5f * (W.x * v + W.y * u);
    float Q  = 0.5f * (W.y * v - W.x * u);
    float ar = Er + P, ai = Ei + Q;
    float br = Er - P, bi = Q - Ei;
    mk = sqrtf(ar * ar + ai * ai);
    mp = sqrtf(br * br + bi * bi);
}

// ---------------------------------------------------------------------------
// Fused kernel: ONE frame per 128-thread block (8 blocks/SM).
// FFT passes on 64 threads (proven fastest); AC in 8-lag chunks, 2 lags/warp.
// ---------------------------------------------------------------------------
__global__ void __launch_bounds__(128, 8) fused_kernel(const float* __restrict__ audio,
                                                       int n, int T) {
    const int tid = threadIdx.x;
    const int t   = blockIdx.x;

    __shared__ __align__(16) float2 bufA[NC];
    __shared__ __align__(16) float2 bufB[NC];
    __shared__ __align__(16) float  ac_s[516];
    __shared__ int found;

    const float2* __restrict__ twm = g_twc.v;
    const int start = t * HOPLEN - 1024;
    const bool refl = (start < 0) || (start + 4096 > n);   // 20 of 8193 blocks

    if (tid == 0) { found = 0; ac_s[512] = 0.0f; }

    // ---- pass1 (S=1,4): inline load -> bufB (swizzled); 64 threads ----------
    if (tid < 64) {
        if (refl) fft_pass16_load<true >(audio, n, start, bufB, twm, tid);
        else      fft_pass16_load<false>(audio, n, start, bufB, twm, tid);
    }
    __syncthreads();
    // ---- pass2 (S=16,64): bufB(swz) -> bufA ---------------------------------
    if (tid < 64)
        fft_pass16<16, true, false>(bufB, bufA, twm, tid);
    __syncthreads();

    // ---- merged pass3 (s=256) + rfft untangle + magnitude -> m (= bufB) -----
    float* m = (float*)bufB;
    {
        const int j  = tid;
        const int b2 = (j == 0) ? 128 : (256 - j);
        const float2* A = bufA;
        float2 Z1[4], Z2[4];
        bfly4(A[j],  A[j + 256],  A[j + 512],  A[j + 768],
              Z1[0], Z1[1], Z1[2], Z1[3]);
        bfly4(A[b2], A[b2 + 256], A[b2 + 512], A[b2 + 768],
              Z2[0], Z2[1], Z2[2], Z2[3]);
        if (j > 0) {
            pairmag(Z1[0], Z2[3], twm[j],       m[j],       m[1024 - j]);
            pairmag(Z1[1], Z2[2], twm[j + 256], m[j + 256], m[768 - j]);
            pairmag(Z2[1], Z1[2], twm[512 - j], m[512 - j], m[512 + j]);
            pairmag(Z2[0], Z1[3], twm[256 - j], m[256 - j], m[768 + j]);
        } else {
            float dummy;
            pairmag(Z1[0], Z1[0], twm[0],   m[0],   m[1024]);
            pairmag(Z1[1], Z1[3], twm[256], m[256], m[768]);
            pairmag(Z1[2], Z1[2], twm[512], m[512], dummy);
            pairmag(Z2[0], Z2[3], twm[128], m[128], m[896]);
            pairmag(Z2[1], Z2[2], twm[384], m[384], m[640]);
        }
        // pad: max index read by AC is 1535
        for (int i = NBINS + tid; i < 1552; i += 128) m[i] = 0.0f;
    }
    __syncthreads();

    // ---- autocorrelation: 8-lag chunks, warp = 2 lags, early exit -----------
    // k=1024 term is provably zero for all lags >= 1 -> 8 k-iterations suffice.
    const int w_f  = tid >> 5;
    const int lane = tid & 31;
    const int kbase = 4 * lane;

    float4 areg[8];
    #pragma unroll
    for (int i = 0; i < 8; ++i)
        areg[i] = *(const float4*)(m + kbase + 128 * i);

    int loLag = 2;
    #pragma unroll 1
    for (int C = 0; C <= 504; C += 8) {
        {
            const int L = C + 2 * w_f;          // this warp's 2 lags: L, L+1
            float2 acc = make_float2(0.f, 0.f);
            #pragma unroll
            for (int i = 0; i < 8; ++i) {
                const float4 a = areg[i];
                const float* bp = m + kbase + 128 * i + L;   // L even -> f2 aligned
                float2 b0 = *(const float2*)bp;
                float2 b1 = *(const float2*)(bp + 2);
                float2 b2 = *(const float2*)(bp + 4);
                acc.x += a.x * b0.x + a.y * b0.y + a.z * b1.x + a.w * b1.y;
                acc.y += a.x * b0.y + a.y * b1.x + a.z * b1.y + a.w * b2.x;
            }
            // 2-sum warp reduction in 5 shuffles
            float ox = __shfl_xor_sync(0xffffffffu, acc.x, 1);
            float oy = __shfl_xor_sync(0xffffffffu, acc.y, 1);
            float val = (lane & 1) ? (acc.y + oy) : (acc.x + ox);
            val += __shfl_xor_sync(0xffffffffu, val, 2);
            val += __shfl_xor_sync(0xffffffffu, val, 4);
            val += __shfl_xor_sync(0xffffffffu, val, 8);
            val += __shfl_xor_sync(0xffffffffu, val, 16);
            if (lane < 2) ac_s[L + lane] = val;
        }
        __syncthreads();

        const int hiLag   = C + 7;
        const int checkHi = (hiLag >= NLAG) ? NLAG : (hiLag - 1);
        if (tid < 16) {
            const int lam = loLag + tid;
            if (lam <= checkHi) {
                float vm = ac_s[lam - 1];
                float v0 = ac_s[lam];
                float vp = ac_s[lam + 1];
                if (v0 > vm && v0 > vp) found = 1;
            }
        }
        loLag = checkHi + 1;
        __syncthreads();
        if (found) break;
    }

    if (tid == 0) g_f0[t] = found ? 50.0f : 0.0f;
}

// ---------------------------------------------------------------------------
// Median-of-5 (PDL secondary; launch overlaps primary drain).
// ---------------------------------------------------------------------------
__global__ void median_kernel(float* __restrict__ out, int T) {
    cudaGridDependencySynchronize();
    int t = blockIdx.x * blockDim.x + threadIdx.x;
    if (t >= T) return;
    float v[5];
    #pragma unroll
    for (int i = 0; i < 5; ++i) {
        int j = t - 2 + i;
        j = max(0, min(T - 1, j));
        v[i] = g_f0[j];
    }
    #pragma unroll
    for (int i = 0; i < 4; ++i)
        #pragma unroll
        for (int j = 0; j < 4 - i; ++j)
            if (v[j] > v[j + 1]) { float tmp = v[j]; v[j] = v[j + 1]; v[j + 1] = tmp; }
    out[t] = v[2];
}

// ---------------------------------------------------------------------------
extern "C" void kernel_launch(void* const* d_in, const int* in_sizes, int n_in,
                              void* d_out, int out_size) {
    const float* audio = (const float*)d_in[0];
    const int n = in_sizes[0];
    const int T = n / HOPLEN + 1;
    float* out = (float*)d_out;

    fused_kernel<<<T, 128>>>(audio, n, T);

    cudaLaunchConfig_t cfg = {};
    cfg.gridDim  = dim3((T + 255) / 256);
    cfg.blockDim = dim3(256);
    cudaLaunchAttribute attrs[1];
    attrs[0].id = cudaLaunchAttributeProgrammaticStreamSerialization;
    attrs[0].val.programmaticStreamSerializationAllowed = 1;
    cfg.attrs = attrs;
    cfg.numAttrs = 1;
    cudaLaunchKernelEx(&cfg, median_kernel, out, T);
}

// round 15
// speedup vs baseline: 1.1800x; 1.1800x over previous
#include <cuda_runtime.h>
#include <math.h>

#define HOPLEN 256
#define NBINS  1025
#define MAXT   8193
#define NLAG   511
#define NC     1024

__device__ float g_f0[MAXT];

// ---------------------------------------------------------------------------
// Compile-time twiddle table: twm[j] = exp(-i*pi*j/1024), j in [0,2048).
// ---------------------------------------------------------------------------
struct alignas(16) TwTab { float2 v[2048]; };

constexpr double tp_sin(double x) {
    double t = x, s = x;
    for (int k = 1; k <= 10; ++k) { t = -t * x * x / ((2.0 * k) * (2.0 * k + 1.0)); s += t; }
    return s;
}
constexpr double tp_cos(double x) {
    double t = 1.0, s = 1.0;
    for (int k = 1; k <= 10; ++k) { t = -t * x * x / ((2.0 * k - 1.0) * (2.0 * k)); s += t; }
    return s;
}
constexpr TwTab make_twtab() {
    TwTab tab{};
    const double PI = 3.14159265358979323846264338327950288;
    for (int j = 0; j < 2048; ++j) {
        int q = (j >> 9) & 3;
        int r = j & 511;
        double c = 0.0, s = 0.0;
        if (r <= 256) { double x = PI * r / 1024.0;         c = tp_cos(x); s = tp_sin(x); }
        else          { double x = PI * (512 - r) / 1024.0; c = tp_sin(x); s = tp_cos(x); }
        double ct = 0.0, st = 0.0;
        switch (q) {
            case 0:  ct = c;  st = s;  break;
            case 1:  ct = -s; st = c;  break;
            case 2:  ct = -c; st = -s; break;
            default: ct = s;  st = -c; break;
        }
        tab.v[j].x = (float)ct;
        tab.v[j].y = (float)(-st);
    }
    return tab;
}
__device__ constexpr TwTab g_twc = make_twtab();

__device__ __forceinline__ float2 cmul(float2 a, float2 b) {
    return make_float2(a.x * b.x - a.y * b.y, a.x * b.y + a.y * b.x);
}
__device__ __forceinline__ int swz(int i) { return i ^ ((i >> 4) & 15); }

// single-MUFU sqrt (rel err ~2^-23; feeds comparisons with O(3%) margins)
__device__ __forceinline__ float sqrt_fast(float x) {
    float r;
    asm("sqrt.approx.f32 %0, %1;" : "=f"(r) : "f"(x));
    return r;
}

// reflect-handling load (boundary blocks only)
__device__ __forceinline__ float2 load_pt_refl(const float* __restrict__ audio, int n,
                                               int start, const float2* __restrict__ twm,
                                               int x) {
    int j0 = 2 * x;
    int i0 = start + j0, i1 = i0 + 1;
    if (i0 < 0) i0 = -i0; else if (i0 >= n) i0 = 2 * n - 2 - i0;
    if (i1 < 0) i1 = -i1; else if (i1 >= n) i1 = 2 * n - 2 - i1;
    float4 tv = *(const float4*)(twm + j0);
    return make_float2(audio[i0] * (0.5f - 0.5f * tv.x),
                       audio[i1] * (0.5f - 0.5f * tv.z));
}
// fast interior load: start even -> float2-aligned vector load, no clamps
__device__ __forceinline__ float2 load_pt_fast(const float2* __restrict__ audio2,
                                               const float2* __restrict__ twm, int x) {
    float2 av = __ldg(audio2 + x);
    float4 tv = *(const float4*)(twm + 2 * x);
    return make_float2(av.x * (0.5f - 0.5f * tv.x),
                       av.y * (0.5f - 0.5f * tv.z));
}

__device__ __forceinline__ void bfly4(float2 a0, float2 a1, float2 a2, float2 a3,
                                      float2& y0, float2& y1, float2& y2, float2& y3) {
    float2 s02 = make_float2(a0.x + a2.x, a0.y + a2.y);
    float2 d02 = make_float2(a0.x - a2.x, a0.y - a2.y);
    float2 s13 = make_float2(a1.x + a3.x, a1.y + a3.y);
    float2 d13 = make_float2(a1.x - a3.x, a1.y - a3.y);
    y0 = make_float2(s02.x + s13.x, s02.y + s13.y);
    y2 = make_float2(s02.x - s13.x, s02.y - s13.y);
    y1 = make_float2(d02.x + d13.y, d02.y - d13.x);
    y3 = make_float2(d02.x - d13.y, d02.y + d13.x);
}

template<int S, bool SWIN, bool SWOUT>
__device__ __forceinline__ void fft_pass16(const float2* __restrict__ src,
                                           float2* __restrict__ dst,
                                           const float2* __restrict__ twm, int c) {
    const int q = c & (S - 1);
    float2 t[4][4];
    #pragma unroll
    for (int j = 0; j < 4; ++j) {
        const int b = c + 64 * j;
        float2 a0 = src[SWIN ? swz(b)       : (b)];
        float2 a1 = src[SWIN ? swz(b + 256) : (b + 256)];
        float2 a2 = src[SWIN ? swz(b + 512) : (b + 512)];
        float2 a3 = src[SWIN ? swz(b + 768) : (b + 768)];
        float2 y0, y1, y2, y3;
        bfly4(a0, a1, a2, a3, y0, y1, y2, y3);
        const int p = b - q;
        t[j][0] = y0;
        t[j][1] = cmul(twm[2 * p], y1);
        t[j][2] = cmul(twm[4 * p], y2);
        t[j][3] = cmul(twm[6 * p], y3);
    }
    #pragma unroll
    for (int rh = 0; rh < 4; ++rh) {
        const int b4 = 4 * c - 3 * q + S * rh;
        const int q4 = b4 & (4 * S - 1);
        const int p4 = b4 - q4;
        float2 y0, y1, y2, y3;
        bfly4(t[0][rh], t[1][rh], t[2][rh], t[3][rh], y0, y1, y2, y3);
        const int base = 4 * p4 + q4;
        dst[SWOUT ? swz(base)          : (base)]          = y0;
        dst[SWOUT ? swz(base + 4 * S)  : (base + 4 * S)]  = cmul(twm[2 * p4], y1);
        dst[SWOUT ? swz(base + 8 * S)  : (base + 8 * S)]  = cmul(twm[4 * p4], y2);
        dst[SWOUT ? swz(base + 12 * S) : (base + 12 * S)] = cmul(twm[6 * p4], y3);
    }
}

template<bool REFL>
__device__ __forceinline__ void fft_pass16_load(const float* __restrict__ audio, int n,
                                                int start, float2* __restrict__ dst,
                                                const float2* __restrict__ twm, int c) {
    const float2* audio2 = (const float2*)(audio + start);   // start even
    float2 t[4][4];
    #pragma unroll
    for (int j = 0; j < 4; ++j) {
        const int b = c + 64 * j;
        float2 a0, a1, a2, a3;
        if (REFL) {
            a0 = load_pt_refl(audio, n, start, twm, b);
            a1 = load_pt_refl(audio, n, start, twm, b + 256);
            a2 = load_pt_refl(audio, n, start, twm, b + 512);
            a3 = load_pt_refl(audio, n, start, twm, b + 768);
        } else {
            a0 = load_pt_fast(audio2, twm, b);
            a1 = load_pt_fast(audio2, twm, b + 256);
            a2 = load_pt_fast(audio2, twm, b + 512);
            a3 = load_pt_fast(audio2, twm, b + 768);
        }
        float2 y0, y1, y2, y3;
        bfly4(a0, a1, a2, a3, y0, y1, y2, y3);
        t[j][0] = y0;
        t[j][1] = cmul(twm[2 * b], y1);
        t[j][2] = cmul(twm[4 * b], y2);
        t[j][3] = cmul(twm[6 * b], y3);
    }
    #pragma unroll
    for (int rh = 0; rh < 4; ++rh) {
        float2 y0, y1, y2, y3;
        bfly4(t[0][rh], t[1][rh], t[2][rh], t[3][rh], y0, y1, y2, y3);
        const int p4 = 4 * c;
        const int base = 4 * p4 + rh;
        dst[swz(base)]      = y0;
        dst[swz(base + 4)]  = cmul(twm[2 * p4], y1);
        dst[swz(base + 8)]  = cmul(twm[4 * p4], y2);
        dst[swz(base + 12)] = cmul(twm[6 * p4], y3);
    }
}

__device__ __forceinline__ void pairmag(float2 Zk, float2 Zm, float2 W,
                                        float& mk, float& mp) {
    float Er = 0.5f * (Zk.x + Zm.x);
    float Ei = 0.5f * (Zk.y - Zm.y);
    float u  = Zk.x - Zm.x;
    float v  = Zk.y + Zm.y;
    float P  = 0.5f * (W.x * v + W.y * u);
    float Q  = 0.5f * (W.y * v - W.x * u);
    float ar = Er + P, ai = Ei + Q;
    float br = Er - P, bi = Q - Ei;
    mk = sqrt_fast(ar * ar + ai * ai);
    mp = sqrt_fast(br * br + bi * bi);
}

// ---------------------------------------------------------------------------
// Fused kernel: ONE frame per 128-thread block (8 blocks/SM).
// (Round-11 structure: 64-thread FFT passes, 16-lag AC chunks.)
// ---------------------------------------------------------------------------
__global__ void __launch_bounds__(128, 8) fused_kernel(const float* __restrict__ audio,
                                                       int n, int T) {
    const int tid = threadIdx.x;
    const int t   = blockIdx.x;

    __shared__ __align__(16) float2 bufA[NC];
    __shared__ __align__(16) float2 bufB[NC];
    __shared__ __align__(16) float  ac_s[516];
    __shared__ int found;

    const float2* __restrict__ twm = g_twc.v;
    const int start = t * HOPLEN - 1024;
    const bool refl = (start < 0) || (start + 4096 > n);   // 20 of 8193 blocks

    if (tid == 0) { found = 0; ac_s[512] = 0.0f; }

    // ---- pass1 (S=1,4): inline load -> bufB (swizzled); 64 threads ----------
    if (tid < 64) {
        if (refl) fft_pass16_load<true >(audio, n, start, bufB, twm, tid);
        else      fft_pass16_load<false>(audio, n, start, bufB, twm, tid);
    }
    __syncthreads();
    // ---- pass2 (S=16,64): bufB(swz) -> bufA ---------------------------------
    if (tid < 64)
        fft_pass16<16, true, false>(bufB, bufA, twm, tid);
    __syncthreads();

    // ---- merged pass3 (s=256) + rfft untangle + magnitude -> m (= bufB) -----
    float* m = (float*)bufB;
    {
        const int j  = tid;
        const int b2 = (j == 0) ? 128 : (256 - j);
        const float2* A = bufA;
        float2 Z1[4], Z2[4];
        bfly4(A[j],  A[j + 256],  A[j + 512],  A[j + 768],
              Z1[0], Z1[1], Z1[2], Z1[3]);
        bfly4(A[b2], A[b2 + 256], A[b2 + 512], A[b2 + 768],
              Z2[0], Z2[1], Z2[2], Z2[3]);
        if (j > 0) {
            pairmag(Z1[0], Z2[3], twm[j],       m[j],       m[1024 - j]);
            pairmag(Z1[1], Z2[2], twm[j + 256], m[j + 256], m[768 - j]);
            pairmag(Z2[1], Z1[2], twm[512 - j], m[512 - j], m[512 + j]);
            pairmag(Z2[0], Z1[3], twm[256 - j], m[256 - j], m[768 + j]);
        } else {
            float dummy;
            pairmag(Z1[0], Z1[0], twm[0],   m[0],   m[1024]);
            pairmag(Z1[1], Z1[3], twm[256], m[256], m[768]);
            pairmag(Z1[2], Z1[2], twm[512], m[512], dummy);
            pairmag(Z2[0], Z2[3], twm[128], m[128], m[896]);
            pairmag(Z2[1], Z2[2], twm[384], m[384], m[640]);
        }
        // pad: max index read by AC is 1538
        for (int i = NBINS + tid; i < 1552; i += 128) m[i] = 0.0f;
    }
    __syncthreads();

    // ---- autocorrelation: 16-lag chunks, warp = 4 lags, early exit ----------
    // k=1024 term is provably zero for all lags >= 1 -> 8 iterations cover it.
    const int w_f  = tid >> 5;
    const int lane = tid & 31;
    const int kbase = 4 * lane;

    float4 areg[8];
    #pragma unroll
    for (int i = 0; i < 8; ++i)
        areg[i] = *(const float4*)(m + kbase + 128 * i);

    int loLag = 2;
    #pragma unroll 1
    for (int C = 0; C <= 496; C += 16) {
        {
            const int L = C + 4 * w_f;
            float4 acc = make_float4(0.f, 0.f, 0.f, 0.f);
            #pragma unroll
            for (int i = 0; i < 8; ++i) {
                const float4 a = areg[i];
                const float* bp = m + kbase + 128 * i + L;
                float4 b0 = *(const float4*)bp;
                float4 b1 = *(const float4*)(bp + 4);
                acc.x += a.x * b0.x + a.y * b0.y + a.z * b0.z + a.w * b0.w;
                acc.y += a.x * b0.y + a.y * b0.z + a.z * b0.w + a.w * b1.x;
                acc.z += a.x * b0.z + a.y * b0.w + a.z * b1.x + a.w * b1.y;
                acc.w += a.x * b0.w + a.y * b1.x + a.z * b1.y + a.w * b1.z;
            }
            float pa, pb;
            {
                float ox = __shfl_xor_sync(0xffffffffu, acc.x, 1);
                float oy = __shfl_xor_sync(0xffffffffu, acc.y, 1);
                float oz = __shfl_xor_sync(0xffffffffu, acc.z, 1);
                float ow = __shfl_xor_sync(0xffffffffu, acc.w, 1);
                bool odd = (lane & 1);
                pa = odd ? (acc.y + oy) : (acc.x + ox);
                pb = odd ? (acc.w + ow) : (acc.z + oz);
            }
            pa += __shfl_xor_sync(0xffffffffu, pa, 2);
            pb += __shfl_xor_sync(0xffffffffu, pb, 2);
            float val = (lane & 2) ? pb : pa;
            val += __shfl_xor_sync(0xffffffffu, val, 4);
            val += __shfl_xor_sync(0xffffffffu, val, 8);
            val += __shfl_xor_sync(0xffffffffu, val, 16);
            if (lane < 4) ac_s[L + lane] = val;
        }
        __syncthreads();

        const int hiLag   = C + 15;
        const int checkHi = (hiLag >= NLAG) ? NLAG : (hiLag - 1);
        if (tid < 32) {
            const int lam = loLag + tid;
            if (lam <= checkHi) {
                float vm = ac_s[lam - 1];
                float v0 = ac_s[lam];
                float vp = ac_s[lam + 1];
                if (v0 > vm && v0 > vp) found = 1;
            }
        }
        loLag = checkHi + 1;
        __syncthreads();
        if (found) break;
    }

    if (tid == 0) g_f0[t] = found ? 50.0f : 0.0f;
}

// ---------------------------------------------------------------------------
// Median-of-5 (PDL secondary; launch overlaps primary drain).
// ---------------------------------------------------------------------------
__global__ void median_kernel(float* __restrict__ out, int T) {
    cudaGridDependencySynchronize();
    int t = blockIdx.x * blockDim.x + threadIdx.x;
    if (t >= T) return;
    float v[5];
    #pragma unroll
    for (int i = 0; i < 5; ++i) {
        int j = t - 2 + i;
        j = max(0, min(T - 1, j));
        v[i] = g_f0[j];
    }
    #pragma unroll
    for (int i = 0; i < 4; ++i)
        #pragma unroll
        for (int j = 0; j < 4 - i; ++j)
            if (v[j] > v[j + 1]) { float tmp = v[j]; v[j] = v[j + 1]; v[j + 1] = tmp; }
    out[t] = v[2];
}

// ---------------------------------------------------------------------------
extern "C" void kernel_launch(void* const* d_in, const int* in_sizes, int n_in,
                              void* d_out, int out_size) {
    const float* audio = (const float*)d_in[0];
    const int n = in_sizes[0];
    const int T = n / HOPLEN + 1;
    float* out = (float*)d_out;

    fused_kernel<<<T, 128>>>(audio, n, T);

    cudaLaunchConfig_t cfg = {};
    cfg.gridDim  = dim3((T + 255) / 256);
    cfg.blockDim = dim3(256);
    cudaLaunchAttribute attrs[1];
    attrs[0].id = cudaLaunchAttributeProgrammaticStreamSerialization;
    attrs[0].val.programmaticStreamSerializationAllowed = 1;
    cfg.attrs = attrs;
    cfg.numAttrs = 1;
    cudaLaunchKernelEx(&cfg, median_kernel, out, T);
}

// round 16
// speedup vs baseline: 1.2147x; 1.0294x over previous
#include <cuda_runtime.h>
#include <math.h>

#define HOPLEN 256
#define NBINS  1025
#define MAXT   8193
#define NLAG   511
#define NC     1024

typedef unsigned long long ull;

__device__ float g_f0[MAXT];

// ---------------------------------------------------------------------------
// Compile-time twiddle table: twm[j] = exp(-i*pi*j/1024), j in [0,2048).
// ---------------------------------------------------------------------------
struct alignas(16) TwTab { float2 v[2048]; };

constexpr double tp_sin(double x) {
    double t = x, s = x;
    for (int k = 1; k <= 10; ++k) { t = -t * x * x / ((2.0 * k) * (2.0 * k + 1.0)); s += t; }
    return s;
}
constexpr double tp_cos(double x) {
    double t = 1.0, s = 1.0;
    for (int k = 1; k <= 10; ++k) { t = -t * x * x / ((2.0 * k - 1.0) * (2.0 * k)); s += t; }
    return s;
}
constexpr TwTab make_twtab() {
    TwTab tab{};
    const double PI = 3.14159265358979323846264338327950288;
    for (int j = 0; j < 2048; ++j) {
        int q = (j >> 9) & 3;
        int r = j & 511;
        double c = 0.0, s = 0.0;
        if (r <= 256) { double x = PI * r / 1024.0;         c = tp_cos(x); s = tp_sin(x); }
        else          { double x = PI * (512 - r) / 1024.0; c = tp_sin(x); s = tp_cos(x); }
        double ct = 0.0, st = 0.0;
        switch (q) {
            case 0:  ct = c;  st = s;  break;
            case 1:  ct = -s; st = c;  break;
            case 2:  ct = -c; st = -s; break;
            default: ct = s;  st = -c; break;
        }
        tab.v[j].x = (float)ct;
        tab.v[j].y = (float)(-st);
    }
    return tab;
}
__device__ constexpr TwTab g_twc = make_twtab();

__device__ __forceinline__ float2 cmul(float2 a, float2 b) {
    return make_float2(a.x * b.x - a.y * b.y, a.x * b.y + a.y * b.x);
}
__device__ __forceinline__ int swz(int i) { return i ^ ((i >> 4) & 15); }

// single-MUFU sqrt (rel err ~2^-23; feeds comparisons with O(3%) margins)
__device__ __forceinline__ float sqrt_fast(float x) {
    float r;
    asm("sqrt.approx.f32 %0, %1;" : "=f"(r) : "f"(x));
    return r;
}

// ---- packed f32x2 helpers (sm_103a) ----------------------------------------
__device__ __forceinline__ ull PK(float2 a) {
    ull r; asm("mov.b64 %0, {%1, %2};" : "=l"(r) : "f"(a.x), "f"(a.y)); return r;
}
__device__ __forceinline__ float2 UPK(ull v) {
    float2 r; asm("mov.b64 {%0, %1}, %2;" : "=f"(r.x), "=f"(r.y) : "l"(v)); return r;
}
__device__ __forceinline__ ull ADD2P(ull a, ull b) {
    ull r; asm("add.rn.f32x2 %0, %1, %2;" : "=l"(r) : "l"(a), "l"(b)); return r;
}
// a - b as fma(b, -1, a): single rounding -> bit-identical to scalar sub
__device__ __forceinline__ ull SUB2P(ull a, ull b) {
    const ull n1 = 0xBF800000BF800000ULL;   // (-1.0f, -1.0f)
    ull r; asm("fma.rn.f32x2 %0, %1, %2, %3;" : "=l"(r) : "l"(b), "l"(n1), "l"(a));
    return r;
}

// radix-4 butterfly via packed f32x2: 8 packed ops vs 16 scalar (bit-exact)
__device__ __forceinline__ void bfly4(float2 A0, float2 A1, float2 A2, float2 A3,
                                      float2& y0, float2& y1, float2& y2, float2& y3) {
    ull a0 = PK(A0), a1 = PK(A1), a2 = PK(A2), a3 = PK(A3);
    ull s02 = ADD2P(a0, a2);
    ull d02 = SUB2P(a0, a2);
    ull s13 = ADD2P(a1, a3);
    ull d13 = SUB2P(a1, a3);
    y0 = UPK(ADD2P(s02, s13));
    y2 = UPK(SUB2P(s02, s13));
    float2 d = UPK(d13);
    ull d13s = PK(make_float2(d.y, d.x));
    float2 u = UPK(ADD2P(d02, d13s));
    float2 v = UPK(SUB2P(d02, d13s));
    y1 = make_float2(u.x, v.y);     // d02 - i*d13
    y3 = make_float2(v.x, u.y);     // d02 + i*d13
}

// reflect-handling load (boundary blocks only)
__device__ __forceinline__ float2 load_pt_refl(const float* __restrict__ audio, int n,
                                               int start, const float2* __restrict__ twm,
                                               int x) {
    int j0 = 2 * x;
    int i0 = start + j0, i1 = i0 + 1;
    if (i0 < 0) i0 = -i0; else if (i0 >= n) i0 = 2 * n - 2 - i0;
    if (i1 < 0) i1 = -i1; else if (i1 >= n) i1 = 2 * n - 2 - i1;
    float4 tv = *(const float4*)(twm + j0);
    return make_float2(audio[i0] * (0.5f - 0.5f * tv.x),
                       audio[i1] * (0.5f - 0.5f * tv.z));
}
// fast interior load: start even -> float2-aligned vector load, no clamps
__device__ __forceinline__ float2 load_pt_fast(const float2* __restrict__ audio2,
                                               const float2* __restrict__ twm, int x) {
    float2 av = __ldg(audio2 + x);
    float4 tv = *(const float4*)(twm + 2 * x);
    return make_float2(av.x * (0.5f - 0.5f * tv.x),
                       av.y * (0.5f - 0.5f * tv.z));
}

template<int S, bool SWIN, bool SWOUT>
__device__ __forceinline__ void fft_pass16(const float2* __restrict__ src,
                                           float2* __restrict__ dst,
                                           const float2* __restrict__ twm, int c) {
    const int q = c & (S - 1);
    float2 t[4][4];
    #pragma unroll
    for (int j = 0; j < 4; ++j) {
        const int b = c + 64 * j;
        float2 a0 = src[SWIN ? swz(b)       : (b)];
        float2 a1 = src[SWIN ? swz(b + 256) : (b + 256)];
        float2 a2 = src[SWIN ? swz(b + 512) : (b + 512)];
        float2 a3 = src[SWIN ? swz(b + 768) : (b + 768)];
        float2 y0, y1, y2, y3;
        bfly4(a0, a1, a2, a3, y0, y1, y2, y3);
        const int p = b - q;
        t[j][0] = y0;
        t[j][1] = cmul(twm[2 * p], y1);
        t[j][2] = cmul(twm[4 * p], y2);
        t[j][3] = cmul(twm[6 * p], y3);
    }
    #pragma unroll
    for (int rh = 0; rh < 4; ++rh) {
        const int b4 = 4 * c - 3 * q + S * rh;
        const int q4 = b4 & (4 * S - 1);
        const int p4 = b4 - q4;
        float2 y0, y1, y2, y3;
        bfly4(t[0][rh], t[1][rh], t[2][rh], t[3][rh], y0, y1, y2, y3);
        const int base = 4 * p4 + q4;
        dst[SWOUT ? swz(base)          : (base)]          = y0;
        dst[SWOUT ? swz(base + 4 * S)  : (base + 4 * S)]  = cmul(twm[2 * p4], y1);
        dst[SWOUT ? swz(base + 8 * S)  : (base + 8 * S)]  = cmul(twm[4 * p4], y2);
        dst[SWOUT ? swz(base + 12 * S) : (base + 12 * S)] = cmul(twm[6 * p4], y3);
    }
}

template<bool REFL>
__device__ __forceinline__ void fft_pass16_load(const float* __restrict__ audio, int n,
                                                int start, float2* __restrict__ dst,
                                                const float2* __restrict__ twm, int c) {
    const float2* audio2 = (const float2*)(audio + start);   // start even
    float2 t[4][4];
    #pragma unroll
    for (int j = 0; j < 4; ++j) {
        const int b = c + 64 * j;
        float2 a0, a1, a2, a3;
        if (REFL) {
            a0 = load_pt_refl(audio, n, start, twm, b);
            a1 = load_pt_refl(audio, n, start, twm, b + 256);
            a2 = load_pt_refl(audio, n, start, twm, b + 512);
            a3 = load_pt_refl(audio, n, start, twm, b + 768);
        } else {
            a0 = load_pt_fast(audio2, twm, b);
            a1 = load_pt_fast(audio2, twm, b + 256);
            a2 = load_pt_fast(audio2, twm, b + 512);
            a3 = load_pt_fast(audio2, twm, b + 768);
        }
        float2 y0, y1, y2, y3;
        bfly4(a0, a1, a2, a3, y0, y1, y2, y3);
        t[j][0] = y0;
        t[j][1] = cmul(twm[2 * b], y1);
        t[j][2] = cmul(twm[4 * b], y2);
        t[j][3] = cmul(twm[6 * b], y3);
    }
    #pragma unroll
    for (int rh = 0; rh < 4; ++rh) {
        float2 y0, y1, y2, y3;
        bfly4(t[0][rh], t[1][rh], t[2][rh], t[3][rh], y0, y1, y2, y3);
        const int p4 = 4 * c;
        const int base = 4 * p4 + rh;
        dst[swz(base)]      = y0;
        dst[swz(base + 4)]  = cmul(twm[2 * p4], y1);
        dst[swz(base + 8)]  = cmul(twm[4 * p4], y2);
        dst[swz(base + 12)] = cmul(twm[6 * p4], y3);
    }
}

// magnitudes scaled by exactly 2x (0.5 factors dropped): ac scales by exactly
// 4x, every strict comparison is invariant, f0 in {0,50} unchanged.
__device__ __forceinline__ void pairmag(float2 Zk, float2 Zm, float2 W,
                                        float& mk, float& mp) {
    float Er = Zk.x + Zm.x;
    float Ei = Zk.y - Zm.y;
    float u  = Zk.x - Zm.x;
    float v  = Zk.y + Zm.y;
    float P  = W.x * v + W.y * u;
    float Q  = W.y * v - W.x * u;
    float ar = Er + P, ai = Ei + Q;
    float br = Er - P, bi = Q - Ei;
    mk = sqrt_fast(ar * ar + ai * ai);
    mp = sqrt_fast(br * br + bi * bi);
}

// ---------------------------------------------------------------------------
// Fused kernel: ONE frame per 128-thread block (8 blocks/SM).
// ---------------------------------------------------------------------------
__global__ void __launch_bounds__(128, 8) fused_kernel(const float* __restrict__ audio,
                                                       int n, int T) {
    const int tid = threadIdx.x;
    const int t   = blockIdx.x;

    __shared__ __align__(16) float2 bufA[NC];
    __shared__ __align__(16) float2 bufB[NC];
    __shared__ __align__(16) float  ac_s[516];

    const float2* __restrict__ twm = g_twc.v;
    const int start = t * HOPLEN - 1024;
    const bool refl = (start < 0) || (start + 4096 > n);   // 20 of 8193 blocks

    if (tid == 0) ac_s[512] = 0.0f;

    // ---- pass1 (S=1,4): inline load -> bufB (swizzled); 64 threads ----------
    if (tid < 64) {
        if (refl) fft_pass16_load<true >(audio, n, start, bufB, twm, tid);
        else      fft_pass16_load<false>(audio, n, start, bufB, twm, tid);
    }
    __syncthreads();
    // ---- pass2 (S=16,64): bufB(swz) -> bufA ---------------------------------
    if (tid < 64)
        fft_pass16<16, true, false>(bufB, bufA, twm, tid);
    __syncthreads();

    // ---- merged pass3 (s=256) + rfft untangle + magnitude -> m (= bufB) -----
    float* m = (float*)bufB;
    {
        const int j  = tid;
        const int b2 = (j == 0) ? 128 : (256 - j);
        const float2* A = bufA;
        float2 Z1[4], Z2[4];
        bfly4(A[j],  A[j + 256],  A[j + 512],  A[j + 768],
              Z1[0], Z1[1], Z1[2], Z1[3]);
        bfly4(A[b2], A[b2 + 256], A[b2 + 512], A[b2 + 768],
              Z2[0], Z2[1], Z2[2], Z2[3]);
        if (j > 0) {
            pairmag(Z1[0], Z2[3], twm[j],       m[j],       m[1024 - j]);
            pairmag(Z1[1], Z2[2], twm[j + 256], m[j + 256], m[768 - j]);
            pairmag(Z2[1], Z1[2], twm[512 - j], m[512 - j], m[512 + j]);
            pairmag(Z2[0], Z1[3], twm[256 - j], m[256 - j], m[768 + j]);
        } else {
            float dummy;
            pairmag(Z1[0], Z1[0], twm[0],   m[0],   m[1024]);
            pairmag(Z1[1], Z1[3], twm[256], m[256], m[768]);
            pairmag(Z1[2], Z1[2], twm[512], m[512], dummy);
            pairmag(Z2[0], Z2[3], twm[128], m[128], m[896]);
            pairmag(Z2[1], Z2[2], twm[384], m[384], m[640]);
        }
        // pad: max index read by AC is 1538
        for (int i = NBINS + tid; i < 1552; i += 128) m[i] = 0.0f;
    }
    __syncthreads();

    // ---- autocorrelation: 16-lag chunks, warp = 4 lags, early exit ----------
    // k=1024 term is provably zero for all lags >= 1 -> 8 iterations cover it.
    const int w_f  = tid >> 5;
    const int lane = tid & 31;
    const int kbase = 4 * lane;

    float4 areg[8];
    #pragma unroll
    for (int i = 0; i < 8; ++i)
        areg[i] = *(const float4*)(m + kbase + 128 * i);

    int cumFound = 0;
    int loLag = 2;
    #pragma unroll 1
    for (int C = 0; C <= 496; C += 16) {
        {
            const int L = C + 4 * w_f;
            float4 acc = make_float4(0.f, 0.f, 0.f, 0.f);
            #pragma unroll
            for (int i = 0; i < 8; ++i) {
                const float4 a = areg[i];
                const float* bp = m + kbase + 128 * i + L;
                float4 b0 = *(const float4*)bp;
                float4 b1 = *(const float4*)(bp + 4);
                acc.x += a.x * b0.x + a.y * b0.y + a.z * b0.z + a.w * b0.w;
                acc.y += a.x * b0.y + a.y * b0.z + a.z * b0.w + a.w * b1.x;
                acc.z += a.x * b0.z + a.y * b0.w + a.z * b1.x + a.w * b1.y;
                acc.w += a.x * b0.w + a.y * b1.x + a.z * b1.y + a.w * b1.z;
            }
            float pa, pb;
            {
                float ox = __shfl_xor_sync(0xffffffffu, acc.x, 1);
                float oy = __shfl_xor_sync(0xffffffffu, acc.y, 1);
                float oz = __shfl_xor_sync(0xffffffffu, acc.z, 1);
                float ow = __shfl_xor_sync(0xffffffffu, acc.w, 1);
                bool odd = (lane & 1);
                pa = odd ? (acc.y + oy) : (acc.x + ox);
                pb = odd ? (acc.w + ow) : (acc.z + oz);
            }
            pa += __shfl_xor_sync(0xffffffffu, pa, 2);
            pb += __shfl_xor_sync(0xffffffffu, pb, 2);
            float val = (lane & 2) ? pb : pa;
            val += __shfl_xor_sync(0xffffffffu, val, 4);
            val += __shfl_xor_sync(0xffffffffu, val, 8);
            val += __shfl_xor_sync(0xffffffffu, val, 16);
            if (lane < 4) ac_s[L + lane] = val;
        }
        __syncthreads();

        const int hiLag   = C + 15;
        const int checkHi = (hiLag >= NLAG) ? NLAG : (hiLag - 1);
        int pred = 0;
        if (tid < 32) {
            const int lam = loLag + tid;
            if (lam <= checkHi) {
                float vm = ac_s[lam - 1];
                float v0 = ac_s[lam];
                float vp = ac_s[lam + 1];
                pred = (v0 > vm && v0 > vp);
            }
        }
        loLag = checkHi + 1;
        cumFound |= __syncthreads_or(pred);   // barrier + block-wide OR fused
        if (cumFound) break;                  // uniform
    }

    if (tid == 0) g_f0[t] = cumFound ? 50.0f : 0.0f;
}

// ---------------------------------------------------------------------------
// Median-of-5 (PDL secondary; launch overlaps primary drain).
// ---------------------------------------------------------------------------
__global__ void median_kernel(float* __restrict__ out, int T) {
    cudaGridDependencySynchronize();
    int t = blockIdx.x * blockDim.x + threadIdx.x;
    if (t >= T) return;
    float v[5];
    #pragma unroll
    for (int i = 0; i < 5; ++i) {
        int j = t - 2 + i;
        j = max(0, min(T - 1, j));
        v[i] = g_f0[j];
    }
    #pragma unroll
    for (int i = 0; i < 4; ++i)
        #pragma unroll
        for (int j = 0; j < 4 - i; ++j)
            if (v[j] > v[j + 1]) { float tmp = v[j]; v[j] = v[j + 1]; v[j + 1] = tmp; }
    out[t] = v[2];
}

// ---------------------------------------------------------------------------
extern "C" void kernel_launch(void* const* d_in, const int* in_sizes, int n_in,
                              void* d_out, int out_size) {
    const float* audio = (const float*)d_in[0];
    const int n = in_sizes[0];
    const int T = n / HOPLEN + 1;
    float* out = (float*)d_out;

    fused_kernel<<<T, 128>>>(audio, n, T);

    cudaLaunchConfig_t cfg = {};
    cfg.gridDim  = dim3((T + 255) / 256);
    cfg.blockDim = dim3(256);
    cudaLaunchAttribute attrs[1];
    attrs[0].id = cudaLaunchAttributeProgrammaticStreamSerialization;
    attrs[0].val.programmaticStreamSerializationAllowed = 1;
    cfg.attrs = attrs;
    cfg.numAttrs = 1;
    cudaLaunchKernelEx(&cfg, median_kernel, out, T);
}